// round 12
// baseline (speedup 1.0000x reference)
#include <cuda_runtime.h>
#include <cuda_bf16.h>
#include <math.h>

// GRNNTransformGated via mma.sync.m16n8k16 bf16 (3-pass split ~ fp32 precision).
// K-outer GEMMs, pre-split weights, ldmatrix fragments, interleaved MMA issue.
// ROWS=32, NT=256 (8 warps, 8n x MT=2), single B buffer with sequential hi/lo
// staging -> 99.6 KB smem -> 2 CTAs/SM for cross-CTA latency hiding.

#define NT 256
#define ROWS 32
#define MT 2
#define SAB 528   // A buf row stride bytes; (528/4)%32=4 -> ldmatrix conflict-free
#define SRB 400   // rx buf row stride bytes; (400/4)%32=4
#define SBB 144   // B k-tile row stride bytes; (144/4)%32=4

__device__ float g_upA[262144 * 64];
__device__ float g_upB[131072 * 64];

// pre-split weights (bf16 hi/lo), [n][K] row-major
__device__ unsigned short g_Wr_hi[36864], g_Wr_lo[36864];
__device__ unsigned short g_Wh_hi[12288], g_Wh_lo[12288];
__device__ unsigned short g_Wz_hi[65536], g_Wz_lo[65536];

__device__ __forceinline__ void split_pack(float a, float b, unsigned& hi, unsigned& lo) {
    __nv_bfloat16 ha = __float2bfloat16(a), hb = __float2bfloat16(b);
    __nv_bfloat16 la = __float2bfloat16(a - __bfloat162float(ha));
    __nv_bfloat16 lb = __float2bfloat16(b - __bfloat162float(hb));
    hi = (unsigned)__bfloat16_as_ushort(ha) | ((unsigned)__bfloat16_as_ushort(hb) << 16);
    lo = (unsigned)__bfloat16_as_ushort(la) | ((unsigned)__bfloat16_as_ushort(lb) << 16);
}
__device__ __forceinline__ float rd_split(const char* hi, const char* lo, int row, int col, int strideB) {
    return __bfloat162float(*(const __nv_bfloat16*)(hi + row * strideB + col * 2)) +
           __bfloat162float(*(const __nv_bfloat16*)(lo + row * strideB + col * 2));
}
__device__ __forceinline__ unsigned smem_u32(const void* p) {
    unsigned a;
    asm("{ .reg .u64 t; cvta.to.shared.u64 t, %1; cvt.u32.u64 %0, t; }" : "=r"(a) : "l"(p));
    return a;
}
__device__ __forceinline__ void mma16816(float* c, const unsigned* a, const unsigned* b) {
    asm volatile("mma.sync.aligned.m16n8k16.row.col.f32.bf16.bf16.f32 "
                 "{%0,%1,%2,%3}, {%4,%5,%6,%7}, {%8,%9}, {%0,%1,%2,%3};"
                 : "+f"(c[0]), "+f"(c[1]), "+f"(c[2]), "+f"(c[3])
                 : "r"(a[0]), "r"(a[1]), "r"(a[2]), "r"(a[3]), "r"(b[0]), "r"(b[1]));
}
#define LDSM_X4(d, addr) \
    asm volatile("ldmatrix.sync.aligned.m8n8.x4.shared.b16 {%0,%1,%2,%3}, [%4];" \
                 : "=r"((d)[0]), "=r"((d)[1]), "=r"((d)[2]), "=r"((d)[3]) : "r"(addr))
#define LDSM_X2(d, addr) \
    asm volatile("ldmatrix.sync.aligned.m8n8.x2.shared.b16 {%0,%1}, [%2];" \
                 : "=r"((d)[0]), "=r"((d)[1]) : "r"(addr))

// ---------------- weight prep: fp32 -> bf16 hi/lo (once per launch) ----------------
__global__ void prep_weights(const float* __restrict__ W_r,
                             const float* __restrict__ W_h,
                             const float* __restrict__ W_z) {
    int i = blockIdx.x * blockDim.x + threadIdx.x;
    float v; unsigned short* ph; unsigned short* pl; int k;
    if (i < 36864)       { v = W_r[i];            ph = g_Wr_hi; pl = g_Wr_lo; k = i; }
    else if (i < 49152)  { v = W_h[i - 36864];    ph = g_Wh_hi; pl = g_Wh_lo; k = i - 36864; }
    else if (i < 114688) { v = W_z[i - 49152];    ph = g_Wz_hi; pl = g_Wz_lo; k = i - 49152; }
    else return;
    __nv_bfloat16 h = __float2bfloat16(v);
    __nv_bfloat16 l = __float2bfloat16(v - __bfloat162float(h));
    ph[k] = __bfloat16_as_ushort(h);
    pl[k] = __bfloat16_as_ushort(l);
}

// stage NR virtual rows x 64 k (one of hi/lo) into single B buffer
__device__ __forceinline__ void stageB(char* B, const unsigned short* __restrict__ W,
                                       int NR, int Ksrc, int k0, int t, bool remap) {
    for (int e = t; e < NR * 8; e += NT) {
        int n = e >> 3, kq = (e & 7) * 8;
        int sr = remap ? (n & 63) : n;                    // stacked W_h: 3 k-tiles as rows
        int sk = remap ? ((n >> 6) * 64 + kq) : (k0 + kq);
        *(uint4*)(B + n * SBB + kq * 2) = *(const uint4*)(W + (size_t)sr * Ksrc + sk);
    }
}

// ---------------- top level (j=12) ----------------
__global__ void grnn_top_kernel(const float* __restrict__ contents,
                                const float* __restrict__ W_u,
                                const float* __restrict__ b_u,
                                float* __restrict__ up, int n) {
    int idx = blockIdx.x * blockDim.x + threadIdx.x;
    if (idx >= n * 64) return;
    int i = idx >> 6, h = idx & 63;
    const float* c = contents + (size_t)i * 7;
    const float* w = W_u + h * 7;
    float acc = b_u[h];
#pragma unroll
    for (int f = 0; f < 7; f++) acc = fmaf(__ldg(c + f), __ldg(w + f), acc);
    up[idx] = fmaxf(acc, 0.f);
}

// ---------------- fused level kernel: 32 rows / block, 2 CTAs / SM ----------------
__global__ __launch_bounds__(NT, 2) void grnn_level_kernel(
    const float* __restrict__ contents,
    const float* __restrict__ up_prev,
    float* __restrict__ up_out,
    const float* __restrict__ W_u, const float* __restrict__ b_u,
    const unsigned short* __restrict__ Wr_hi, const unsigned short* __restrict__ Wr_lo,
    const float* __restrict__ b_r,
    const unsigned short* __restrict__ Wh_hi, const unsigned short* __restrict__ Wh_lo,
    const float* __restrict__ b_h,
    const unsigned short* __restrict__ Wz_hi, const unsigned short* __restrict__ Wz_lo,
    const float* __restrict__ b_z)
{
    constexpr int OF_ALO = ROWS * SAB;                   // 16896
    constexpr int OF_RHI = OF_ALO + ROWS * SAB;          // 33792
    constexpr int OF_RLO = OF_RHI + ROWS * SRB;          // 46592
    constexpr int OF_B   = OF_RLO + ROWS * SRB;          // 59392
    constexpr int OF_CS  = OF_B + 256 * SBB;             // 96256
    constexpr int OF_WU  = OF_CS + ROWS * 8 * 4;         // 97280
    constexpr int OF_BUS = OF_WU + 64 * 8 * 4;           // 99328

    extern __shared__ char sm[];
    char* AHI = sm;            char* ALO = sm + OF_ALO;
    char* RHI = sm + OF_RHI;   char* RLO = sm + OF_RLO;
    char* Bb  = sm + OF_B;
    float* cs  = (float*)(sm + OF_CS);
    float* wu  = (float*)(sm + OF_WU);
    float* bus = (float*)(sm + OF_BUS);

    const unsigned smb = smem_u32(sm);
    const unsigned uAHI = smb, uALO = smb + OF_ALO;
    const unsigned uRHI = smb + OF_RHI, uRLO = smb + OF_RLO;
    const unsigned uB   = smb + OF_B;

    const int t = threadIdx.x, lane = t & 31, wn = t >> 5;    // 8 warps, wm = 0
    const int g = lane >> 2, tg = lane & 3, l16 = lane & 15;
    const unsigned aSel = ((lane >> 4) & 1) * 16;
    const unsigned bSel = ((lane >> 3) & 1) * 16;
    const int r0 = blockIdx.x * ROWS;

    // ---- phase 0a ----
    for (int idx = t; idx < ROWS * 7; idx += NT) {
        int i = idx / 7, f = idx % 7;
        cs[i * 8 + f] = contents[(size_t)(r0 + i) * 7 + f];
    }
    for (int idx = t; idx < 64 * 7; idx += NT) wu[(idx / 7) * 8 + (idx % 7)] = W_u[idx];
    if (t < 64) bus[t] = b_u[t];
    for (int idx = t; idx < ROWS * 32; idx += NT) {
        int i = idx >> 5, q = idx & 31, side = q >> 4, qq = q & 15;
        float4 v = *(const float4*)(up_prev + ((size_t)2 * (r0 + i) + side) * 64 + qq * 4);
        unsigned h0, l0, h1, l1;
        split_pack(v.x, v.y, h0, l0); split_pack(v.z, v.w, h1, l1);
        int col = 64 + side * 64 + qq * 4;
        *(uint2*)(AHI + i * SAB + col * 2) = make_uint2(h0, h1);
        *(uint2*)(ALO + i * SAB + col * 2) = make_uint2(l0, l1);
    }
    __syncthreads();
    // ---- phase 0b: u = relu(c @ W_u^T + b_u) -> cols 192..255 ----
    for (int idx = t; idx < ROWS * 32; idx += NT) {
        int i = idx >> 5, cp = idx & 31;
        float a0 = bus[2 * cp], a1 = bus[2 * cp + 1];
#pragma unroll
        for (int f = 0; f < 7; f++) {
            float cv = cs[i * 8 + f];
            a0 = fmaf(cv, wu[(2 * cp) * 8 + f], a0);
            a1 = fmaf(cv, wu[(2 * cp + 1) * 8 + f], a1);
        }
        a0 = fmaxf(a0, 0.f); a1 = fmaxf(a1, 0.f);
        unsigned hi, lo; split_pack(a0, a1, hi, lo);
        *(unsigned*)(AHI + i * SAB + (192 + 2 * cp) * 2) = hi;
        *(unsigned*)(ALO + i * SAB + (192 + 2 * cp) * 2) = lo;
    }

    // ---- GEMM1: rx = sigmoid(hhu @ W_r^T + b_r) * hhu; K-outer, seq hi/lo B ----
    float acc1[3][MT][4] = {};
    for (int kc = 0; kc < 3; kc++) {
        __syncthreads();                       // prior B reads / phase0 writes done
        stageB(Bb, Wr_hi, 192, 192, kc * 64, t, false);
        __syncthreads();
#pragma unroll
        for (int kk = 0; kk < 4; kk++) {       // hi phase: ah*bh, al*bh
            unsigned ah[MT][4], al[MT][4];
#pragma unroll
            for (int mt = 0; mt < MT; mt++) {
                unsigned off = (unsigned)((mt * 16 + l16) * SAB
                                          + (64 + kc * 64 + kk * 16) * 2) + aSel;
                LDSM_X4(ah[mt], uAHI + off);
                LDSM_X4(al[mt], uALO + off);
            }
            unsigned bh[3][2];
#pragma unroll
            for (int c = 0; c < 3; c++) {
                unsigned bo = (unsigned)((c * 64 + wn * 8 + (lane & 7)) * SBB + kk * 32) + bSel;
                LDSM_X2(bh[c], uB + bo);
            }
#pragma unroll
            for (int c = 0; c < 3; c++)
#pragma unroll
                for (int mt = 0; mt < MT; mt++) mma16816(acc1[c][mt], ah[mt], bh[c]);
#pragma unroll
            for (int c = 0; c < 3; c++)
#pragma unroll
                for (int mt = 0; mt < MT; mt++) mma16816(acc1[c][mt], al[mt], bh[c]);
        }
        __syncthreads();
        stageB(Bb, Wr_lo, 192, 192, kc * 64, t, false);
        __syncthreads();
#pragma unroll
        for (int kk = 0; kk < 4; kk++) {       // lo phase: ah*bl
            unsigned ah[MT][4];
#pragma unroll
            for (int mt = 0; mt < MT; mt++) {
                unsigned off = (unsigned)((mt * 16 + l16) * SAB
                                          + (64 + kc * 64 + kk * 16) * 2) + aSel;
                LDSM_X4(ah[mt], uAHI + off);
            }
            unsigned bl[3][2];
#pragma unroll
            for (int c = 0; c < 3; c++) {
                unsigned bo = (unsigned)((c * 64 + wn * 8 + (lane & 7)) * SBB + kk * 32) + bSel;
                LDSM_X2(bl[c], uB + bo);
            }
#pragma unroll
            for (int c = 0; c < 3; c++)
#pragma unroll
                for (int mt = 0; mt < MT; mt++) mma16816(acc1[c][mt], ah[mt], bl[c]);
        }
    }
    // epilogue 1: rx -> RHI/RLO (per-thread-unique rows/cols; sync comes with next stage)
#pragma unroll
    for (int c = 0; c < 3; c++)
#pragma unroll
        for (int mt = 0; mt < MT; mt++)
#pragma unroll
            for (int rs = 0; rs < 2; rs++) {
                int row = mt * 16 + g + rs * 8;
                int o0 = c * 64 + wn * 8 + 2 * tg;
                float z0 = acc1[c][mt][rs * 2 + 0] + __ldg(b_r + o0);
                float z1 = acc1[c][mt][rs * 2 + 1] + __ldg(b_r + o0 + 1);
                float s0 = 1.f / (1.f + __expf(-z0));
                float s1 = 1.f / (1.f + __expf(-z1));
                float x0 = s0 * rd_split(AHI, ALO, row, 64 + o0, SAB);
                float x1 = s1 * rd_split(AHI, ALO, row, 64 + o0 + 1, SAB);
                unsigned hi, lo; split_pack(x0, x1, hi, lo);
                *(unsigned*)(RHI + row * SRB + o0 * 2) = hi;
                *(unsigned*)(RLO + row * SRB + o0 * 2) = lo;
            }

    // ---- GEMM2: h_H = relu(rx @ W_h^T + b_h) -> AHI cols 0..63; seq hi/lo B ----
    float acc2[MT][4] = {};
    __syncthreads();                           // rx visible + GEMM1 B reads done
    stageB(Bb, Wh_hi, 192, 192, 0, t, true);   // stacked: 3 k-tiles as virtual rows
    __syncthreads();
#pragma unroll
    for (int kk = 0; kk < 12; kk++) {
        int kt = kk >> 2, k2 = kk & 3;
        unsigned ah[MT][4], al[MT][4];
#pragma unroll
        for (int mt = 0; mt < MT; mt++) {
            unsigned off = (unsigned)((mt * 16 + l16) * SRB + kk * 32) + aSel;
            LDSM_X4(ah[mt], uRHI + off);
            LDSM_X4(al[mt], uRLO + off);
        }
        unsigned bo = (unsigned)((kt * 64 + wn * 8 + (lane & 7)) * SBB + k2 * 32) + bSel;
        unsigned bh[2];
        LDSM_X2(bh, uB + bo);
#pragma unroll
        for (int mt = 0; mt < MT; mt++) mma16816(acc2[mt], ah[mt], bh);
#pragma unroll
        for (int mt = 0; mt < MT; mt++) mma16816(acc2[mt], al[mt], bh);
    }
    __syncthreads();
    stageB(Bb, Wh_lo, 192, 192, 0, t, true);
    __syncthreads();
#pragma unroll
    for (int kk = 0; kk < 12; kk++) {
        int kt = kk >> 2, k2 = kk & 3;
        unsigned ah[MT][4];
#pragma unroll
        for (int mt = 0; mt < MT; mt++) {
            unsigned off = (unsigned)((mt * 16 + l16) * SRB + kk * 32) + aSel;
            LDSM_X4(ah[mt], uRHI + off);
        }
        unsigned bo = (unsigned)((kt * 64 + wn * 8 + (lane & 7)) * SBB + k2 * 32) + bSel;
        unsigned bl[2];
        LDSM_X2(bl, uB + bo);
#pragma unroll
        for (int mt = 0; mt < MT; mt++) mma16816(acc2[mt], ah[mt], bl);
    }
    // epilogue 2: hH -> AHI/ALO cols 0..63
#pragma unroll
    for (int mt = 0; mt < MT; mt++)
#pragma unroll
        for (int rs = 0; rs < 2; rs++) {
            int row = mt * 16 + g + rs * 8;
            int h0 = wn * 8 + 2 * tg;
            float v0 = fmaxf(acc2[mt][rs * 2 + 0] + __ldg(b_h + h0), 0.f);
            float v1 = fmaxf(acc2[mt][rs * 2 + 1] + __ldg(b_h + h0 + 1), 0.f);
            unsigned hi, lo; split_pack(v0, v1, hi, lo);
            *(unsigned*)(AHI + row * SAB + h0 * 2) = hi;
            *(unsigned*)(ALO + row * SAB + h0 * 2) = lo;
        }

    // ---- GEMM3: z = [h_H | hhu] @ W_z^T + b_z; K-outer, seq hi/lo B ----
    float acc3[4][MT][4] = {};
    for (int kc = 0; kc < 4; kc++) {
        __syncthreads();                       // hH visible (kc=0) / prior B reads done
        stageB(Bb, Wz_hi, 256, 256, kc * 64, t, false);
        __syncthreads();
#pragma unroll
        for (int kk = 0; kk < 4; kk++) {
            unsigned ah[MT][4], al[MT][4];
#pragma unroll
            for (int mt = 0; mt < MT; mt++) {
                unsigned off = (unsigned)((mt * 16 + l16) * SAB
                                          + (kc * 64 + kk * 16) * 2) + aSel;
                LDSM_X4(ah[mt], uAHI + off);
                LDSM_X4(al[mt], uALO + off);
            }
            unsigned bh[4][2];
#pragma unroll
            for (int c = 0; c < 4; c++) {
                unsigned bo = (unsigned)((c * 64 + wn * 8 + (lane & 7)) * SBB + kk * 32) + bSel;
                LDSM_X2(bh[c], uB + bo);
            }
#pragma unroll
            for (int c = 0; c < 4; c++)
#pragma unroll
                for (int mt = 0; mt < MT; mt++) mma16816(acc3[c][mt], ah[mt], bh[c]);
#pragma unroll
            for (int c = 0; c < 4; c++)
#pragma unroll
                for (int mt = 0; mt < MT; mt++) mma16816(acc3[c][mt], al[mt], bh[c]);
        }
        __syncthreads();
        stageB(Bb, Wz_lo, 256, 256, kc * 64, t, false);
        __syncthreads();
#pragma unroll
        for (int kk = 0; kk < 4; kk++) {
            unsigned ah[MT][4];
#pragma unroll
            for (int mt = 0; mt < MT; mt++) {
                unsigned off = (unsigned)((mt * 16 + l16) * SAB
                                          + (kc * 64 + kk * 16) * 2) + aSel;
                LDSM_X4(ah[mt], uAHI + off);
            }
            unsigned bl[4][2];
#pragma unroll
            for (int c = 0; c < 4; c++) {
                unsigned bo = (unsigned)((c * 64 + wn * 8 + (lane & 7)) * SBB + kk * 32) + bSel;
                LDSM_X2(bl[c], uB + bo);
            }
#pragma unroll
            for (int c = 0; c < 4; c++)
#pragma unroll
                for (int mt = 0; mt < MT; mt++) mma16816(acc3[c][mt], ah[mt], bl[c]);
        }
    }

    // ---- final: softmax over 4 groups, gated combine, store fp32 ----
#pragma unroll
    for (int mt = 0; mt < MT; mt++)
#pragma unroll
        for (int rs = 0; rs < 2; rs++) {
            int row = mt * 16 + g + rs * 8;
            int h0 = wn * 8 + 2 * tg;
            float res[2];
#pragma unroll
            for (int e = 0; e < 2; e++) {
                int h = h0 + e;
                float v0 = acc3[0][mt][rs * 2 + e] + __ldg(b_z + h);
                float v1 = acc3[1][mt][rs * 2 + e] + __ldg(b_z + 64 + h);
                float v2 = acc3[2][mt][rs * 2 + e] + __ldg(b_z + 128 + h);
                float v3 = acc3[3][mt][rs * 2 + e] + __ldg(b_z + 192 + h);
                float mx = fmaxf(fmaxf(v0, v1), fmaxf(v2, v3));
                float e0 = __expf(v0 - mx), e1 = __expf(v1 - mx);
                float e2 = __expf(v2 - mx), e3 = __expf(v3 - mx);
                float inv = 1.f / (e0 + e1 + e2 + e3);
                float hh = rd_split(AHI, ALO, row, h, SAB);
                float hl = rd_split(AHI, ALO, row, 64 + h, SAB);
                float hr = rd_split(AHI, ALO, row, 128 + h, SAB);
                float uu = rd_split(AHI, ALO, row, 192 + h, SAB);
                res[e] = (e0 * hh + e1 * hl + e2 * hr + e3 * uu) * inv;
            }
            *(float2*)(up_out + (size_t)(r0 + row) * 64 + h0) = make_float2(res[0], res[1]);
        }
}

static const int SMEM_BYTES = 99584;

extern "C" void kernel_launch(void* const* d_in, const int* in_sizes, int n_in,
                              void* d_out, int out_size) {
    const float* contents = (const float*)d_in[0];
    const float* W_u = (const float*)d_in[1];
    const float* b_u = (const float*)d_in[2];
    const float* W_r = (const float*)d_in[3];
    const float* b_r = (const float*)d_in[4];
    const float* W_h = (const float*)d_in[5];
    const float* b_h = (const float*)d_in[6];
    const float* W_z = (const float*)d_in[7];
    const float* b_z = (const float*)d_in[8];
    float* out = (float*)d_out;

    float *upA = nullptr, *upB = nullptr;
    cudaGetSymbolAddress((void**)&upA, g_upA);
    cudaGetSymbolAddress((void**)&upB, g_upB);
    unsigned short *wrh, *wrl, *whh, *whl, *wzh, *wzl;
    cudaGetSymbolAddress((void**)&wrh, g_Wr_hi); cudaGetSymbolAddress((void**)&wrl, g_Wr_lo);
    cudaGetSymbolAddress((void**)&whh, g_Wh_hi); cudaGetSymbolAddress((void**)&whl, g_Wh_lo);
    cudaGetSymbolAddress((void**)&wzh, g_Wz_hi); cudaGetSymbolAddress((void**)&wzl, g_Wz_lo);

    cudaFuncSetAttribute(grnn_level_kernel,
                         cudaFuncAttributeMaxDynamicSharedMemorySize, SMEM_BYTES);

    prep_weights<<<(114688 + 255) / 256, 256>>>(W_r, W_h, W_z);

    // Level 12 (top): up = u
    {
        int n = 64 << 12;
        size_t off = (size_t)64 * ((1 << 12) - 1) * 7;
        int total = n * 64;
        grnn_top_kernel<<<(total + 255) / 256, 256>>>(contents + off, W_u, b_u, upA, n);
    }

    // Levels 11..0
    const float* prev = upA;
    for (int j = 11; j >= 0; j--) {
        int n = 64 << j;
        size_t off = (size_t)64 * ((1 << j) - 1) * 7;
        float* outp = (j == 0) ? out : ((j & 1) ? upB : upA);
        grnn_level_kernel<<<n / ROWS, NT, SMEM_BYTES>>>(
            contents + off, prev, outp,
            W_u, b_u, wrh, wrl, b_r, whh, whl, b_h, wzh, wzl, b_z);
        prev = outp;
    }
}